// round 5
// baseline (speedup 1.0000x reference)
#include <cuda_runtime.h>
#include <cuda_bf16.h>
#include <math.h>
#include <stdint.h>

// ---------------- problem constants ----------------
#define NN   50000
#define EE   1600000
#define GG   64

// ---------------- device scratch (no allocation allowed) ----------------
__device__ float g_h0[(size_t)NN * 128];
__device__ float g_h1[(size_t)NN * 128];
__device__ float g_hf[(size_t)NN * 128];
__device__ float g_dinv[NN];
__device__ int   g_deg[NN];
__device__ int   g_off[NN + 1];
__device__ int   g_cur[NN];
__device__ int   g_srcv[EE + NN];
__device__ int   g_bsum[256];
__device__ int   g_boff[256];
__device__ __nv_bfloat16 g_bhe[128 * 1024];      // embed B hi  [n][k]
__device__ __nv_bfloat16 g_ble[128 * 1024];      // embed B lo
__device__ __nv_bfloat16 g_bhm[3 * 128 * 2048];  // mp B hi x3
__device__ __nv_bfloat16 g_blm[3 * 128 * 2048];  // mp B lo x3
__device__ float g_wtr[2048 * 32];               // readout [k][o] fp32
__device__ float g_sums[GG * 128];
__device__ float g_cnts[GG];

// ---------------- helpers ----------------
__device__ __forceinline__ uint32_t smem_to_u32(const void* p) {
    uint32_t a;
    asm("{ .reg .u64 t; cvta.to.shared.u64 t, %1; cvt.u32.u64 %0, t; }" : "=r"(a) : "l"(p));
    return a;
}
#define SWZ(x) ((x) ^ (((x) >> 3) & 0x70))

#define LDSM4(R, addr)                                                           \
    asm volatile("ldmatrix.sync.aligned.m8n8.x4.shared.b16 {%0,%1,%2,%3}, [%4];" \
                 : "=r"((R)[0]), "=r"((R)[1]), "=r"((R)[2]), "=r"((R)[3])        \
                 : "r"(addr))
#define LDSM2(R, addr)                                                           \
    asm volatile("ldmatrix.sync.aligned.m8n8.x2.shared.b16 {%0,%1}, [%2];"       \
                 : "=r"((R)[0]), "=r"((R)[1]) : "r"(addr))
#define MMA16816(D, A, B)                                                        \
    asm volatile("mma.sync.aligned.m16n8k16.row.col.f32.bf16.bf16.f32 "          \
                 "{%0,%1,%2,%3}, {%4,%5,%6,%7}, {%8,%9}, {%0,%1,%2,%3};"         \
                 : "+f"((D)[0]), "+f"((D)[1]), "+f"((D)[2]), "+f"((D)[3])        \
                 : "r"((A)[0]), "r"((A)[1]), "r"((A)[2]), "r"((A)[3]),           \
                   "r"((B)[0]), "r"((B)[1]))

// ---------------- small utility kernels ----------------
__global__ void zero_i32(int* __restrict__ p, int n) {
    int i = blockIdx.x * blockDim.x + threadIdx.x;
    if (i < n) p[i] = 0;
}
__global__ void zero_f32(float* __restrict__ p, int n) {
    int i = blockIdx.x * blockDim.x + threadIdx.x;
    if (i < n) p[i] = 0.0f;
}
__global__ void count_deg(const int* __restrict__ ecol, int* __restrict__ deg) {
    int e = blockIdx.x * blockDim.x + threadIdx.x;
    if (e < EE) atomicAdd(&deg[ecol[e]], 1);
}
__global__ void compute_dinv(const int* __restrict__ deg, float* __restrict__ dinv) {
    int i = blockIdx.x * blockDim.x + threadIdx.x;
    if (i < NN) dinv[i] = rsqrtf((float)(deg[i] + 1));
}

// ---- parallel exclusive scan of (deg+1): 3 kernels ----
__global__ void deg_bsum(const int* __restrict__ deg, int* __restrict__ bsum) {
    __shared__ int sh[256];
    int t = threadIdx.x;
    int i = blockIdx.x * 256 + t;
    sh[t] = (i < NN) ? deg[i] + 1 : 0;
    __syncthreads();
    for (int d = 128; d > 0; d >>= 1) {
        if (t < d) sh[t] += sh[t + d];
        __syncthreads();
    }
    if (t == 0) bsum[blockIdx.x] = sh[0];
}
__global__ void scan_bsum(const int* __restrict__ bsum, int* __restrict__ boff,
                          int nb, int* __restrict__ off) {
    __shared__ int sh[256];
    int t = threadIdx.x;
    int v = (t < nb) ? bsum[t] : 0;
    sh[t] = v;
    __syncthreads();
    for (int d = 1; d < 256; d <<= 1) {
        int u = (t >= d) ? sh[t - d] : 0;
        __syncthreads();
        sh[t] += u;
        __syncthreads();
    }
    if (t < nb) boff[t] = sh[t] - v;
    if (t == 0) off[NN] = EE + NN;
}
__global__ void scan_write(const int* __restrict__ deg, const int* __restrict__ boff,
                           int* __restrict__ off, int* __restrict__ cur) {
    __shared__ int sh[256];
    int t = threadIdx.x;
    int i = blockIdx.x * 256 + t;
    int v = (i < NN) ? deg[i] + 1 : 0;
    sh[t] = v;
    __syncthreads();
    for (int d = 1; d < 256; d <<= 1) {
        int u = (t >= d) ? sh[t - d] : 0;
        __syncthreads();
        sh[t] += u;
        __syncthreads();
    }
    if (i < NN) {
        int o = boff[blockIdx.x] + sh[t] - v;
        off[i] = o;
        cur[i] = o;
    }
}

__global__ void fill_csr(const int* __restrict__ erow, const int* __restrict__ ecol,
                         int* __restrict__ cur, int* __restrict__ srcv) {
    int e = blockIdx.x * blockDim.x + threadIdx.x;
    if (e >= EE + NN) return;
    int r, c;
    if (e < EE) { r = erow[e]; c = ecol[e]; }
    else        { r = c = e - EE; }
    int p = atomicAdd(&cur[c], 1);
    srcv[p] = r;
}

// W[2][out=128][in][8] -> B[n][k] bf16 hi/lo, k = i*16 + t*8 + h
__global__ void make_b(const float* __restrict__ W, __nv_bfloat16* __restrict__ bhi,
                       __nv_bfloat16* __restrict__ blo, int in_dim) {
    int idx = blockIdx.x * blockDim.x + threadIdx.x;
    int K = in_dim * 16;
    if (idx >= 128 * K) return;
    int n = idx / K;
    int k = idx % K;
    int h = k & 7, t = (k >> 3) & 1, i = k >> 4;
    float w = W[(((size_t)t * 128 + n) * in_dim + i) * 8 + h];
    __nv_bfloat16 hi = __float2bfloat16(w);
    __nv_bfloat16 lo = __float2bfloat16(w - __bfloat162float(hi));
    bhi[idx] = hi;
    blo[idx] = lo;
}

// readout weights W[2][32][128][8] -> Wt[k][o] fp32
__global__ void transpose_wr(const float* __restrict__ W, float* __restrict__ Wt) {
    int idx = blockIdx.x * blockDim.x + threadIdx.x;
    if (idx >= 2048 * 32) return;
    int o = idx % 32;
    int k = idx / 32;
    int h = k & 7, t = (k >> 3) & 1, i = k >> 4;
    Wt[idx] = W[(((size_t)t * 32 + o) * 128 + i) * 8 + h];
}

// ---------------- bf16 hi/lo packing ----------------
__device__ __forceinline__ void cvt8(const float* f, uint4& hi, uint4& lo) {
    uint32_t h[4], l[4];
#pragma unroll
    for (int j = 0; j < 4; ++j) {
        float a = f[2 * j], b = f[2 * j + 1];
        __nv_bfloat16 ah = __float2bfloat16(a), bh = __float2bfloat16(b);
        float ar = a - __bfloat162float(ah);
        float br = b - __bfloat162float(bh);
        __nv_bfloat162 hp; hp.x = ah; hp.y = bh;
        __nv_bfloat162 lp = __floats2bfloat162_rn(ar, br);
        h[j] = *reinterpret_cast<uint32_t*>(&hp);
        l[j] = *reinterpret_cast<uint32_t*>(&lp);
    }
    hi = make_uint4(h[0], h[1], h[2], h[3]);
    lo = make_uint4(l[0], l[1], l[2], l[3]);
}

// ---------------- HMMA KAN GEMM (M-tile 64) ----------------
// out[row][n] = sum_k phi(in[row])[k] * B[n][k]; block tile 64x128, K = in_dim*16.
// 3-term bf16 hi/lo split (AhBh + AlBh + AhBl), fp32 accumulators.
__global__ __launch_bounds__(256, 2)
void kan_hmma(const float* __restrict__ in, int in_dim,
              const __nv_bfloat16* __restrict__ bhi, const __nv_bfloat16* __restrict__ blo,
              const float* __restrict__ in_scale, const float* __restrict__ out_scale,
              float* __restrict__ out) {
    extern __shared__ char smem[];
    const uint32_t smem_base = smem_to_u32(smem);
    const int A_HI = 0, A_LO = 8192, B_HI = 16384, B_LO = 32768;

    const int tid  = threadIdx.x;
    const int wid  = tid >> 5, lane = tid & 31;
    const int row0 = blockIdx.x * 64;

    // warp tile: m-offset (wid>>2)*32, n-offset (wid&3)*32
    const int m0 = (wid >> 2) * 32;
    const int n0 = (wid & 3) * 32;

    float acc[2][4][4];
#pragma unroll
    for (int a = 0; a < 2; a++)
#pragma unroll
        for (int b = 0; b < 4; b++)
#pragma unroll
            for (int c2 = 0; c2 < 4; c2++) acc[a][b][c2] = 0.0f;

    const int arow = tid & 63;
    const int ail  = tid >> 6;       // feature index 0..3 within 4-chunk
    const int grow = row0 + arow;
    const bool rv  = grow < NN;
    const float isc = (rv && in_scale) ? in_scale[grow] : 1.0f;
    const int Kb = in_dim * 32;      // B row stride in bytes
    const int nchunks = in_dim / 4;  // 64 k per chunk

    for (int c = 0; c < nchunks; ++c) {
        __syncthreads();
        // --- A tile: phi expansion, bf16 hi/lo, SW128 swizzled ---
        {
            float x = rv ? in[(size_t)grow * in_dim + c * 4 + ail] * isc : 0.0f;
            float s1, c1;
            sincosf(x, &s1, &c1);
            float cv[8], sv[8];
            cv[0] = c1; sv[0] = s1;
            const float t2 = 2.0f * c1;
            float cp = 1.0f, sp = 0.0f;
#pragma unroll
            for (int h = 1; h < 8; ++h) {
                float cn = t2 * cv[h - 1] - cp;
                float sn = t2 * sv[h - 1] - sp;
                cp = cv[h - 1]; sp = sv[h - 1];
                cv[h] = cn; sv[h] = sn;
            }
            uint4 chi, clo, shi, slo;
            cvt8(cv, chi, clo);
            cvt8(sv, shi, slo);
            const uint32_t bo = (uint32_t)(arow * 128 + ail * 32);
            *reinterpret_cast<uint4*>(smem + A_HI + SWZ(bo))      = chi;
            *reinterpret_cast<uint4*>(smem + A_LO + SWZ(bo))      = clo;
            *reinterpret_cast<uint4*>(smem + A_HI + SWZ(bo + 16)) = shi;
            *reinterpret_cast<uint4*>(smem + A_LO + SWZ(bo + 16)) = slo;
        }
        // --- B tile: 128 n-rows x 64 bf16 ---
        {
            const char* ph = (const char*)bhi + c * 128;
            const char* pl = (const char*)blo + c * 128;
#pragma unroll
            for (int r = 0; r < 4; ++r) {
                int idx = tid + 256 * r;
                int n = idx >> 3, seg = idx & 7;
                uint32_t so = SWZ((uint32_t)(n * 128 + seg * 16));
                *reinterpret_cast<uint4*>(smem + B_HI + so) =
                    *reinterpret_cast<const uint4*>(ph + (size_t)n * Kb + seg * 16);
                *reinterpret_cast<uint4*>(smem + B_LO + so) =
                    *reinterpret_cast<const uint4*>(pl + (size_t)n * Kb + seg * 16);
            }
        }
        __syncthreads();
        // --- compute: 4 k16 steps ---
#pragma unroll
        for (int kk = 0; kk < 4; ++kk) {
            const uint32_t kb = kk * 32;
            uint32_t bh[4][2], bl[4][2];
#pragma unroll
            for (int nt = 0; nt < 4; ++nt) {
                uint32_t addr = smem_base + SWZ((uint32_t)((n0 + nt * 8 + (lane & 7)) * 128 + kb + (((lane & 15) >> 3) & 1) * 16));
                LDSM2(bh[nt], addr + B_HI);
                LDSM2(bl[nt], addr + B_LO);
            }
#pragma unroll
            for (int mt = 0; mt < 2; ++mt) {
                uint32_t addr = smem_base + SWZ((uint32_t)((m0 + mt * 16 + (lane & 15)) * 128 + kb + (lane >> 4) * 16));
                uint32_t ah[4], al[4];
                LDSM4(ah, addr + A_HI);
                LDSM4(al, addr + A_LO);
#pragma unroll
                for (int nt = 0; nt < 4; ++nt) {
                    MMA16816(acc[mt][nt], ah, bh[nt]);
                    MMA16816(acc[mt][nt], al, bh[nt]);
                    MMA16816(acc[mt][nt], ah, bl[nt]);
                }
            }
        }
    }

    // --- epilogue ---
    const int g4 = lane >> 2, t4 = lane & 3;
#pragma unroll
    for (int mt = 0; mt < 2; ++mt) {
        int r0 = row0 + m0 + mt * 16 + g4;
        int r1 = r0 + 8;
        float sc0 = 1.0f, sc1 = 1.0f;
        bool v0 = r0 < NN, v1 = r1 < NN;
        if (out_scale) {
            if (v0) sc0 = out_scale[r0];
            if (v1) sc1 = out_scale[r1];
        }
#pragma unroll
        for (int nt = 0; nt < 4; ++nt) {
            int col = n0 + nt * 8 + t4 * 2;
            if (v0) {
                float2* p = reinterpret_cast<float2*>(out + (size_t)r0 * 128 + col);
                *p = make_float2(acc[mt][nt][0] * sc0, acc[mt][nt][1] * sc0);
            }
            if (v1) {
                float2* p = reinterpret_cast<float2*>(out + (size_t)r1 * 128 + col);
                *p = make_float2(acc[mt][nt][2] * sc1, acc[mt][nt][3] * sc1);
            }
        }
    }
}

// ---------------- CSR aggregation ----------------
__global__ void aggregate(const float* __restrict__ hf,
                          const int* __restrict__ off, const int* __restrict__ srcv,
                          float* __restrict__ out) {
    int warp = (blockIdx.x * blockDim.x + threadIdx.x) >> 5;
    int lane = threadIdx.x & 31;
    if (warp >= NN) return;
    int e  = off[warp];
    int e1 = off[warp + 1];
    float4 a0 = make_float4(0.f, 0.f, 0.f, 0.f);
    float4 a1 = make_float4(0.f, 0.f, 0.f, 0.f);
    for (; e + 1 < e1; e += 2) {
        int r0 = __ldg(&srcv[e]);
        int r1 = __ldg(&srcv[e + 1]);
        float4 v0 = *reinterpret_cast<const float4*>(hf + (size_t)r0 * 128 + lane * 4);
        float4 v1 = *reinterpret_cast<const float4*>(hf + (size_t)r1 * 128 + lane * 4);
        a0.x += v0.x; a0.y += v0.y; a0.z += v0.z; a0.w += v0.w;
        a1.x += v1.x; a1.y += v1.y; a1.z += v1.z; a1.w += v1.w;
    }
    if (e < e1) {
        int r0 = __ldg(&srcv[e]);
        float4 v0 = *reinterpret_cast<const float4*>(hf + (size_t)r0 * 128 + lane * 4);
        a0.x += v0.x; a0.y += v0.y; a0.z += v0.z; a0.w += v0.w;
    }
    a0.x += a1.x; a0.y += a1.y; a0.z += a1.z; a0.w += a1.w;
    *reinterpret_cast<float4*>(out + (size_t)warp * 128 + lane * 4) = a0;
}

// ---------------- pooling ----------------
__global__ void pool_kernel(const float* __restrict__ h, const int* __restrict__ batch,
                            const float* __restrict__ dinv,
                            float* __restrict__ sums, float* __restrict__ cnts) {
    const int PER = 25;
    int warp = (blockIdx.x * blockDim.x + threadIdx.x) >> 5;
    int lane = threadIdx.x & 31;
    int n0 = warp * PER;
    if (n0 >= NN) return;
    int n1 = n0 + PER;
    if (n1 > NN) n1 = NN;
    float4 acc = make_float4(0.f, 0.f, 0.f, 0.f);
    float cnt = 0.f;
    int cg = batch[n0];
    for (int n = n0; n < n1; n++) {
        int g = batch[n];
        if (g != cg) {
            float* p = sums + (size_t)cg * 128 + lane * 4;
            atomicAdd(p + 0, acc.x); atomicAdd(p + 1, acc.y);
            atomicAdd(p + 2, acc.z); atomicAdd(p + 3, acc.w);
            if (lane == 0) atomicAdd(&cnts[cg], cnt);
            acc = make_float4(0.f, 0.f, 0.f, 0.f);
            cnt = 0.f; cg = g;
        }
        float w = dinv[n];
        float4 v = *reinterpret_cast<const float4*>(h + (size_t)n * 128 + lane * 4);
        acc.x += w * v.x; acc.y += w * v.y; acc.z += w * v.z; acc.w += w * v.w;
        cnt += 1.f;
    }
    float* p = sums + (size_t)cg * 128 + lane * 4;
    atomicAdd(p + 0, acc.x); atomicAdd(p + 1, acc.y);
    atomicAdd(p + 2, acc.z); atomicAdd(p + 3, acc.w);
    if (lane == 0) atomicAdd(&cnts[cg], cnt);
}

// ---------------- readout ----------------
__global__ void readout_kernel(const float* __restrict__ sums, const float* __restrict__ cnts,
                               const float* __restrict__ Wt,
                               float* __restrict__ out) {
    __shared__ float phi[2048];
    __shared__ float red[4][32];
    const int g = blockIdx.x;
    const int tid = threadIdx.x;     // 128 threads
    float cnt = fmaxf(cnts[g], 1.0f);
    float x = sums[(size_t)g * 128 + tid] / cnt;
    float s1, c1;
    sincosf(x, &s1, &c1);
    const float twoc = 2.0f * c1;
    float cp = 1.0f, sp = 0.0f, cc = c1, ss = s1;
#pragma unroll
    for (int h = 0; h < 8; h++) {
        phi[tid * 16 + h]     = cc;
        phi[tid * 16 + 8 + h] = ss;
        float cn = twoc * cc - cp;
        float sn = twoc * ss - sp;
        cp = cc; sp = ss; cc = cn; ss = sn;
    }
    __syncthreads();
    const int o = tid & 31;
    const int part = tid >> 5;
    float acc = 0.f;
    int k0 = part * 512;
#pragma unroll 8
    for (int k = k0; k < k0 + 512; k++) acc += phi[k] * Wt[k * 32 + o];
    red[part][o] = acc;
    __syncthreads();
    if (tid < 32)
        out[(size_t)g * 32 + tid] = red[0][tid] + red[1][tid] + red[2][tid] + red[3][tid];
}

// ---------------- launch ----------------
extern "C" void kernel_launch(void* const* d_in, const int* in_sizes, int n_in,
                              void* d_out, int out_size) {
    const float* features = (const float*)d_in[0];   // [N,64]
    const int*   edges    = (const int*)d_in[1];     // [2,E]
    const int*   batch    = (const int*)d_in[2];     // [N]
    const float* W_embed  = (const float*)d_in[3];   // [2,128,64,8]
    const float* W_mp     = (const float*)d_in[4];   // [3,2,128,128,8]
    const float* W_read   = (const float*)d_in[5];   // [2,32,128,8]
    float* out = (float*)d_out;                      // [64,32]

    float *h0, *h1, *hf, *dinv, *wtr, *sums, *cnts;
    int *deg, *off, *cur, *srcv, *bsum, *boff;
    __nv_bfloat16 *bhe, *ble, *bhm, *blm;
    cudaGetSymbolAddress((void**)&h0,   g_h0);
    cudaGetSymbolAddress((void**)&h1,   g_h1);
    cudaGetSymbolAddress((void**)&hf,   g_hf);
    cudaGetSymbolAddress((void**)&dinv, g_dinv);
    cudaGetSymbolAddress((void**)&deg,  g_deg);
    cudaGetSymbolAddress((void**)&off,  g_off);
    cudaGetSymbolAddress((void**)&cur,  g_cur);
    cudaGetSymbolAddress((void**)&srcv, g_srcv);
    cudaGetSymbolAddress((void**)&bsum, g_bsum);
    cudaGetSymbolAddress((void**)&boff, g_boff);
    cudaGetSymbolAddress((void**)&bhe,  g_bhe);
    cudaGetSymbolAddress((void**)&ble,  g_ble);
    cudaGetSymbolAddress((void**)&bhm,  g_bhm);
    cudaGetSymbolAddress((void**)&blm,  g_blm);
    cudaGetSymbolAddress((void**)&wtr,  g_wtr);
    cudaGetSymbolAddress((void**)&sums, g_sums);
    cudaGetSymbolAddress((void**)&cnts, g_cnts);

    const int* erow = edges;
    const int* ecol = edges + EE;

    cudaFuncSetAttribute(kan_hmma, cudaFuncAttributeMaxDynamicSharedMemorySize, 49152);

    const int gblocks = (NN + 63) / 64;   // 782
    const int agg_blocks = (NN * 32 + 255) / 256;
    const size_t SMB = 49152;

    // ---- weight prep first (5 launches) so launch #6 = embed GEMM for ncu -s 5 ----
    make_b<<<(128 * 1024 + 255) / 256, 256>>>(W_embed, bhe, ble, 64);
    for (int l = 0; l < 3; l++)
        make_b<<<(128 * 2048 + 255) / 256, 256>>>(
            W_mp + (size_t)l * 2 * 128 * 128 * 8,
            bhm + (size_t)l * 128 * 2048, blm + (size_t)l * 128 * 2048, 128);
    transpose_wr<<<(2048 * 32 + 255) / 256, 256>>>(W_read, wtr);

    // embed: h0 = kan(features)   [launch #6 — ncu target]
    kan_hmma<<<gblocks, 256, SMB>>>(features, 64, bhe, ble, nullptr, nullptr, h0);

    // ---- CSR build (destination-indexed, self loops appended) ----
    zero_i32<<<(NN + 255) / 256, 256>>>(deg, NN);
    count_deg<<<(EE + 255) / 256, 256>>>(ecol, deg);
    compute_dinv<<<(NN + 255) / 256, 256>>>(deg, dinv);
    const int nb = (NN + 255) / 256;  // 196
    deg_bsum<<<nb, 256>>>(deg, bsum);
    scan_bsum<<<1, 256>>>(bsum, boff, nb, off);
    scan_write<<<nb, 256>>>(deg, boff, off, cur);
    fill_csr<<<(EE + NN + 255) / 256, 256>>>(erow, ecol, cur, srcv);

    // mp 0
    kan_hmma<<<gblocks, 256, SMB>>>(h0, 128, bhm, blm, nullptr, dinv, hf);
    aggregate<<<agg_blocks, 256>>>(hf, off, srcv, h1);
    // mp 1
    kan_hmma<<<gblocks, 256, SMB>>>(h1, 128, bhm + 128 * 2048, blm + 128 * 2048, dinv, dinv, hf);
    aggregate<<<agg_blocks, 256>>>(hf, off, srcv, h0);
    // mp 2
    kan_hmma<<<gblocks, 256, SMB>>>(h0, 128, bhm + 2 * 128 * 2048, blm + 2 * 128 * 2048, dinv, dinv, hf);
    aggregate<<<agg_blocks, 256>>>(hf, off, srcv, h1);

    // pool + readout
    zero_f32<<<(GG * 128 + 255) / 256, 256>>>(sums, GG * 128);
    zero_f32<<<1, 64>>>(cnts, GG);
    pool_kernel<<<250, 256>>>(h1, batch, dinv, sums, cnts);
    readout_kernel<<<GG, 128>>>(sums, cnts, wtr, out);
}

// round 7
// speedup vs baseline: 1.0546x; 1.0546x over previous
#include <cuda_runtime.h>
#include <cuda_bf16.h>
#include <math.h>
#include <stdint.h>

// ---------------- problem constants ----------------
#define NN   50000
#define EE   1600000
#define GG   64

// ---------------- device scratch (no allocation allowed) ----------------
__device__ float g_h0[(size_t)NN * 128];
__device__ float g_h1[(size_t)NN * 128];
__device__ float g_hf[(size_t)NN * 128];
__device__ float g_dinv[NN];
__device__ int   g_deg[NN];
__device__ int   g_off[NN + 1];
__device__ int   g_cur[NN];
__device__ int   g_srcv[EE + NN];
__device__ int   g_bsum[256];
__device__ int   g_boff[256];
__device__ __nv_bfloat16 g_bhe[128 * 1024];      // embed B hi  [n][k]
__device__ __nv_bfloat16 g_ble[128 * 1024];      // embed B lo
__device__ __nv_bfloat16 g_bhm[3 * 128 * 2048];  // mp B hi x3
__device__ __nv_bfloat16 g_blm[3 * 128 * 2048];  // mp B lo x3
__device__ float g_wtr[2048 * 32];               // readout [k][o] fp32
__device__ float g_sums[GG * 128];
__device__ float g_cnts[GG];

// ---------------- helpers ----------------
__device__ __forceinline__ uint32_t smem_to_u32(const void* p) {
    uint32_t a;
    asm("{ .reg .u64 t; cvta.to.shared.u64 t, %1; cvt.u32.u64 %0, t; }" : "=r"(a) : "l"(p));
    return a;
}
#define SWZ(x) ((x) ^ (((x) >> 3) & 0x70))

#define LDSM4(R, addr)                                                           \
    asm volatile("ldmatrix.sync.aligned.m8n8.x4.shared.b16 {%0,%1,%2,%3}, [%4];" \
                 : "=r"((R)[0]), "=r"((R)[1]), "=r"((R)[2]), "=r"((R)[3])        \
                 : "r"(addr))
#define LDSM2(R, addr)                                                           \
    asm volatile("ldmatrix.sync.aligned.m8n8.x2.shared.b16 {%0,%1}, [%2];"       \
                 : "=r"((R)[0]), "=r"((R)[1]) : "r"(addr))
#define MMA16816(D, A, B)                                                        \
    asm volatile("mma.sync.aligned.m16n8k16.row.col.f32.bf16.bf16.f32 "          \
                 "{%0,%1,%2,%3}, {%4,%5,%6,%7}, {%8,%9}, {%0,%1,%2,%3};"         \
                 : "+f"((D)[0]), "+f"((D)[1]), "+f"((D)[2]), "+f"((D)[3])        \
                 : "r"((A)[0]), "r"((A)[1]), "r"((A)[2]), "r"((A)[3]),           \
                   "r"((B)[0]), "r"((B)[1]))
#define CP_ASYNC16(sa, gp)                                                       \
    asm volatile("cp.async.ca.shared.global [%0], [%1], 16;" :: "r"(sa), "l"(gp))
#define CP_COMMIT() asm volatile("cp.async.commit_group;" ::: "memory")
#define CP_WAIT1()  asm volatile("cp.async.wait_group 1;" ::: "memory")

// ---------------- prep kernels ----------------
__global__ void count_deg(const int* __restrict__ ecol, int* __restrict__ deg) {
    int e = blockIdx.x * blockDim.x + threadIdx.x;
    if (e < EE) atomicAdd(&deg[ecol[e]], 1);
}

// ---- parallel exclusive scan of (deg+1), dinv fused ----
__global__ void deg_bsum(const int* __restrict__ deg, int* __restrict__ bsum,
                         float* __restrict__ dinv) {
    __shared__ int sh[256];
    int t = threadIdx.x;
    int i = blockIdx.x * 256 + t;
    int d = (i < NN) ? deg[i] + 1 : 0;
    if (i < NN) dinv[i] = rsqrtf((float)d);
    sh[t] = d;
    __syncthreads();
    for (int s = 128; s > 0; s >>= 1) {
        if (t < s) sh[t] += sh[t + s];
        __syncthreads();
    }
    if (t == 0) bsum[blockIdx.x] = sh[0];
}
__global__ void scan_bsum(const int* __restrict__ bsum, int* __restrict__ boff,
                          int nb, int* __restrict__ off) {
    __shared__ int sh[256];
    int t = threadIdx.x;
    int v = (t < nb) ? bsum[t] : 0;
    sh[t] = v;
    __syncthreads();
    for (int d = 1; d < 256; d <<= 1) {
        int u = (t >= d) ? sh[t - d] : 0;
        __syncthreads();
        sh[t] += u;
        __syncthreads();
    }
    if (t < nb) boff[t] = sh[t] - v;
    if (t == 0) off[NN] = EE + NN;
}
__global__ void scan_write(const int* __restrict__ deg, const int* __restrict__ boff,
                           int* __restrict__ off, int* __restrict__ cur) {
    __shared__ int sh[256];
    int t = threadIdx.x;
    int i = blockIdx.x * 256 + t;
    int v = (i < NN) ? deg[i] + 1 : 0;
    sh[t] = v;
    __syncthreads();
    for (int d = 1; d < 256; d <<= 1) {
        int u = (t >= d) ? sh[t - d] : 0;
        __syncthreads();
        sh[t] += u;
        __syncthreads();
    }
    if (i < NN) {
        int o = boff[blockIdx.x] + sh[t] - v;
        off[i] = o;
        cur[i] = o;
    }
}
__global__ void fill_csr(const int* __restrict__ erow, const int* __restrict__ ecol,
                         int* __restrict__ cur, int* __restrict__ srcv) {
    int e = blockIdx.x * blockDim.x + threadIdx.x;
    if (e >= EE + NN) return;
    int r, c;
    if (e < EE) { r = erow[e]; c = ecol[e]; }
    else        { r = c = e - EE; }
    int p = atomicAdd(&cur[c], 1);
    srcv[p] = r;
}

// W[2][out=128][in][8] -> B[n][k] bf16 hi/lo, k = i*16 + t*8 + h
// Embed variant also zeroes deg / sums / cnts (fused inits).
__global__ void make_b_embed(const float* __restrict__ W, __nv_bfloat16* __restrict__ bhi,
                             __nv_bfloat16* __restrict__ blo,
                             int* __restrict__ deg, float* __restrict__ sums,
                             float* __restrict__ cnts) {
    const int in_dim = 64;
    int idx = blockIdx.x * blockDim.x + threadIdx.x;
    if (idx < NN) deg[idx] = 0;
    if (idx < GG * 128) sums[idx] = 0.0f;
    if (idx < GG) cnts[idx] = 0.0f;
    int K = in_dim * 16;
    if (idx >= 128 * K) return;
    int n = idx / K;
    int k = idx % K;
    int h = k & 7, t = (k >> 3) & 1, i = k >> 4;
    float w = W[(((size_t)t * 128 + n) * in_dim + i) * 8 + h];
    __nv_bfloat16 hi = __float2bfloat16(w);
    __nv_bfloat16 lo = __float2bfloat16(w - __bfloat162float(hi));
    bhi[idx] = hi;
    blo[idx] = lo;
}
__global__ void make_b(const float* __restrict__ W, __nv_bfloat16* __restrict__ bhi,
                       __nv_bfloat16* __restrict__ blo, int in_dim) {
    int idx = blockIdx.x * blockDim.x + threadIdx.x;
    int K = in_dim * 16;
    if (idx >= 128 * K) return;
    int n = idx / K;
    int k = idx % K;
    int h = k & 7, t = (k >> 3) & 1, i = k >> 4;
    float w = W[(((size_t)t * 128 + n) * in_dim + i) * 8 + h];
    __nv_bfloat16 hi = __float2bfloat16(w);
    __nv_bfloat16 lo = __float2bfloat16(w - __bfloat162float(hi));
    bhi[idx] = hi;
    blo[idx] = lo;
}

// readout weights W[2][32][128][8] -> Wt[k][o] fp32
__global__ void transpose_wr(const float* __restrict__ W, float* __restrict__ Wt) {
    int idx = blockIdx.x * blockDim.x + threadIdx.x;
    if (idx >= 2048 * 32) return;
    int o = idx % 32;
    int k = idx / 32;
    int h = k & 7, t = (k >> 3) & 1, i = k >> 4;
    Wt[idx] = W[(((size_t)t * 32 + o) * 128 + i) * 8 + h];
}

// ---------------- bf16 hi/lo packing ----------------
__device__ __forceinline__ void cvt8(const float* f, uint4& hi, uint4& lo) {
    uint32_t h[4], l[4];
#pragma unroll
    for (int j = 0; j < 4; ++j) {
        float a = f[2 * j], b = f[2 * j + 1];
        __nv_bfloat16 ah = __float2bfloat16(a), bh = __float2bfloat16(b);
        float ar = a - __bfloat162float(ah);
        float br = b - __bfloat162float(bh);
        __nv_bfloat162 hp; hp.x = ah; hp.y = bh;
        __nv_bfloat162 lp = __floats2bfloat162_rn(ar, br);
        h[j] = *reinterpret_cast<uint32_t*>(&hp);
        l[j] = *reinterpret_cast<uint32_t*>(&lp);
    }
    hi = make_uint4(h[0], h[1], h[2], h[3]);
    lo = make_uint4(l[0], l[1], l[2], l[3]);
}

// ---------------- HMMA KAN GEMM (M128, bf16 3-term, cp.async B double-buffer) ----
// out[row][n] = sum_k phi(in[row])[k] * B[n][k]; block tile 128x128, K = in_dim*16.
// A = Ah + Al (bf16 hi/lo), B = Bh + Bl; 3 MMAs per k-step (AhBh + AlBh + AhBl).
__global__ __launch_bounds__(256, 2)
void kan_hmma(const float* __restrict__ in, int in_dim,
              const __nv_bfloat16* __restrict__ bhi, const __nv_bfloat16* __restrict__ blo,
              const float* __restrict__ in_scale, const float* __restrict__ out_scale,
              float* __restrict__ out) {
    extern __shared__ char smem[];
    const uint32_t smem_base = smem_to_u32(smem);
    const int A_HI = 0, A_LO = 16384;
    // B stages: stage s hi at 32768 + s*32768, lo at 49152 + s*32768
    const int B_HI0 = 32768, B_LO0 = 49152;

    const int tid  = threadIdx.x;
    const int wid  = tid >> 5, lane = tid & 31;
    const int row0 = blockIdx.x * 128;

    const int m0 = (wid >> 2) * 64;
    const int n0 = (wid & 3) * 32;

    float acc[4][4][4];
#pragma unroll
    for (int a = 0; a < 4; a++)
#pragma unroll
        for (int b = 0; b < 4; b++)
#pragma unroll
            for (int c2 = 0; c2 < 4; c2++) acc[a][b][c2] = 0.0f;

    const int arow = tid & 127;
    const int ail  = tid >> 7;       // handles features ail and ail+2 of each 4-chunk
    const int grow = row0 + arow;
    const bool rv  = grow < NN;
    const float isc = (rv && in_scale) ? in_scale[grow] : 1.0f;
    const int Kb = in_dim * 32;      // B row stride in bytes
    const int nchunks = in_dim / 4;  // 64 k per chunk

    // per-thread B-load addressing (8 x 16B per stage per chunk)
    const int bn0 = tid >> 3, bseg = tid & 7;   // (n, 16B-segment) for r=0

    // prologue: B(0) -> stage 0
    {
        const char* ph = (const char*)bhi;
        const char* pl = (const char*)blo;
#pragma unroll
        for (int r = 0; r < 4; ++r) {
            int n = bn0 + 32 * r;
            uint32_t so = SWZ((uint32_t)(n * 128 + bseg * 16));
            CP_ASYNC16(smem_base + B_HI0 + so, ph + (size_t)n * Kb + bseg * 16);
            CP_ASYNC16(smem_base + B_LO0 + so, pl + (size_t)n * Kb + bseg * 16);
        }
        CP_COMMIT();
    }

    for (int c = 0; c < nchunks; ++c) {
        __syncthreads();   // all MMA(c-1) finished -> A and B-stage[(c+1)&1] safe to write
        // --- prefetch B(c+1) into the other stage ---
        if (c + 1 < nchunks) {
            const int st = ((c + 1) & 1) * 32768;
            const char* ph = (const char*)bhi + (c + 1) * 128;
            const char* pl = (const char*)blo + (c + 1) * 128;
#pragma unroll
            for (int r = 0; r < 4; ++r) {
                int n = bn0 + 32 * r;
                uint32_t so = SWZ((uint32_t)(n * 128 + bseg * 16));
                CP_ASYNC16(smem_base + B_HI0 + st + so, ph + (size_t)n * Kb + bseg * 16);
                CP_ASYNC16(smem_base + B_LO0 + st + so, pl + (size_t)n * Kb + bseg * 16);
            }
        }
        CP_COMMIT();       // one group per iteration (possibly empty on last)
        // --- A tile: phi expansion, bf16 hi/lo, SW128 swizzled ---
#pragma unroll
        for (int q = 0; q < 2; ++q) {
            const int il = ail + 2 * q;
            float x = rv ? in[(size_t)grow * in_dim + c * 4 + il] * isc : 0.0f;
            float s1, c1;
            sincosf(x, &s1, &c1);
            float cv[8], sv[8];
            cv[0] = c1; sv[0] = s1;
            const float t2 = 2.0f * c1;
            float cp = 1.0f, sp = 0.0f;
#pragma unroll
            for (int h = 1; h < 8; ++h) {
                float cn = t2 * cv[h - 1] - cp;
                float sn = t2 * sv[h - 1] - sp;
                cp = cv[h - 1]; sp = sv[h - 1];
                cv[h] = cn; sv[h] = sn;
            }
            uint4 chi, clo, shi, slo;
            cvt8(cv, chi, clo);
            cvt8(sv, shi, slo);
            const uint32_t bo = (uint32_t)(arow * 128 + il * 32);
            *reinterpret_cast<uint4*>(smem + A_HI + SWZ(bo))      = chi;
            *reinterpret_cast<uint4*>(smem + A_LO + SWZ(bo))      = clo;
            *reinterpret_cast<uint4*>(smem + A_HI + SWZ(bo + 16)) = shi;
            *reinterpret_cast<uint4*>(smem + A_LO + SWZ(bo + 16)) = slo;
        }
        CP_WAIT1();        // B(c) landed (B(c+1) may still be in flight)
        __syncthreads();
        // --- compute: 4 k16 steps, 3 MMAs each ---
        const int BH = B_HI0 + (c & 1) * 32768;
        const int BL = B_LO0 + (c & 1) * 32768;
#pragma unroll
        for (int kk = 0; kk < 4; ++kk) {
            const uint32_t kb = kk * 32;
            uint32_t bh[4][2], bl[4][2];
#pragma unroll
            for (int nt = 0; nt < 4; ++nt) {
                uint32_t addr = smem_base + SWZ((uint32_t)((n0 + nt * 8 + (lane & 7)) * 128 + kb + (((lane & 15) >> 3) & 1) * 16));
                LDSM2(bh[nt], addr + BH);
                LDSM2(bl[nt], addr + BL);
            }
#pragma unroll
            for (int mt = 0; mt < 4; ++mt) {
                uint32_t addr = smem_base + SWZ((uint32_t)((m0 + mt * 16 + (lane & 15)) * 128 + kb + (lane >> 4) * 16));
                uint32_t ah[4], al[4];
                LDSM4(ah, addr + A_HI);
                LDSM4(al, addr + A_LO);
#pragma unroll
                for (int nt = 0; nt < 4; ++nt) {
                    MMA16816(acc[mt][nt], ah, bh[nt]);
                    MMA16816(acc[mt][nt], al, bh[nt]);
                    MMA16816(acc[mt][nt], ah, bl[nt]);
                }
            }
        }
    }

    // --- epilogue ---
    const int g4 = lane >> 2, t4 = lane & 3;
#pragma unroll
    for (int mt = 0; mt < 4; ++mt) {
        int r0 = row0 + m0 + mt * 16 + g4;
        int r1 = r0 + 8;
        float sc0 = 1.0f, sc1 = 1.0f;
        bool v0 = r0 < NN, v1 = r1 < NN;
        if (out_scale) {
            if (v0) sc0 = out_scale[r0];
            if (v1) sc1 = out_scale[r1];
        }
#pragma unroll
        for (int nt = 0; nt < 4; ++nt) {
            int col = n0 + nt * 8 + t4 * 2;
            if (v0) {
                float2* p = reinterpret_cast<float2*>(out + (size_t)r0 * 128 + col);
                *p = make_float2(acc[mt][nt][0] * sc0, acc[mt][nt][1] * sc0);
            }
            if (v1) {
                float2* p = reinterpret_cast<float2*>(out + (size_t)r1 * 128 + col);
                *p = make_float2(acc[mt][nt][2] * sc1, acc[mt][nt][3] * sc1);
            }
        }
    }
}

// ---------------- CSR aggregation ----------------
__global__ void aggregate(const float* __restrict__ hf,
                          const int* __restrict__ off, const int* __restrict__ srcv,
                          float* __restrict__ out) {
    int warp = (blockIdx.x * blockDim.x + threadIdx.x) >> 5;
    int lane = threadIdx.x & 31;
    if (warp >= NN) return;
    int e  = off[warp];
    int e1 = off[warp + 1];
    float4 a0 = make_float4(0.f, 0.f, 0.f, 0.f);
    float4 a1 = make_float4(0.f, 0.f, 0.f, 0.f);
    for (; e + 1 < e1; e += 2) {
        int r0 = __ldg(&srcv[e]);
        int r1 = __ldg(&srcv[e + 1]);
        float4 v0 = *reinterpret_cast<const float4*>(hf + (size_t)r0 * 128 + lane * 4);
        float4 v1 = *reinterpret_cast<const float4*>(hf + (size_t)r1 * 128 + lane * 4);
        a0.x += v0.x; a0.y += v0.y; a0.z += v0.z; a0.w += v0.w;
        a1.x += v1.x; a1.y += v1.y; a1.z += v1.z; a1.w += v1.w;
    }
    if (e < e1) {
        int r0 = __ldg(&srcv[e]);
        float4 v0 = *reinterpret_cast<const float4*>(hf + (size_t)r0 * 128 + lane * 4);
        a0.x += v0.x; a0.y += v0.y; a0.z += v0.z; a0.w += v0.w;
    }
    a0.x += a1.x; a0.y += a1.y; a0.z += a1.z; a0.w += a1.w;
    *reinterpret_cast<float4*>(out + (size_t)warp * 128 + lane * 4) = a0;
}

// ---------------- pooling ----------------
__global__ void pool_kernel(const float* __restrict__ h, const int* __restrict__ batch,
                            const float* __restrict__ dinv,
                            float* __restrict__ sums, float* __restrict__ cnts) {
    const int PER = 25;
    int warp = (blockIdx.x * blockDim.x + threadIdx.x) >> 5;
    int lane = threadIdx.x & 31;
    int n0 = warp * PER;
    if (n0 >= NN) return;
    int n1 = n0 + PER;
    if (n1 > NN) n1 = NN;
    float4 acc = make_float4(0.f, 0.f, 0.f, 0.f);
    float cnt = 0.f;
    int cg = batch[n0];
    for (int n = n0; n < n1; n++) {
        int g = batch[n];
        if (g != cg) {
            float* p = sums + (size_t)cg * 128 + lane * 4;
            atomicAdd(p + 0, acc.x); atomicAdd(p + 1, acc.y);
            atomicAdd(p + 2, acc.z); atomicAdd(p + 3, acc.w);
            if (lane == 0) atomicAdd(&cnts[cg], cnt);
            acc = make_float4(0.f, 0.f, 0.f, 0.f);
            cnt = 0.f; cg = g;
        }
        float w = dinv[n];
        float4 v = *reinterpret_cast<const float4*>(h + (size_t)n * 128 + lane * 4);
        acc.x += w * v.x; acc.y += w * v.y; acc.z += w * v.z; acc.w += w * v.w;
        cnt += 1.f;
    }
    float* p = sums + (size_t)cg * 128 + lane * 4;
    atomicAdd(p + 0, acc.x); atomicAdd(p + 1, acc.y);
    atomicAdd(p + 2, acc.z); atomicAdd(p + 3, acc.w);
    if (lane == 0) atomicAdd(&cnts[cg], cnt);
}

// ---------------- readout ----------------
__global__ void readout_kernel(const float* __restrict__ sums, const float* __restrict__ cnts,
                               const float* __restrict__ Wt,
                               float* __restrict__ out) {
    __shared__ float phi[2048];
    __shared__ float red[4][32];
    const int g = blockIdx.x;
    const int tid = threadIdx.x;     // 128 threads
    float cnt = fmaxf(cnts[g], 1.0f);
    float x = sums[(size_t)g * 128 + tid] / cnt;
    float s1, c1;
    sincosf(x, &s1, &c1);
    const float twoc = 2.0f * c1;
    float cp = 1.0f, sp = 0.0f, cc = c1, ss = s1;
#pragma unroll
    for (int h = 0; h < 8; h++) {
        phi[tid * 16 + h]     = cc;
        phi[tid * 16 + 8 + h] = ss;
        float cn = twoc * cc - cp;
        float sn = twoc * ss - sp;
        cp = cc; sp = ss; cc = cn; ss = sn;
    }
    __syncthreads();
    const int o = tid & 31;
    const int part = tid >> 5;
    float acc = 0.f;
    int k0 = part * 512;
#pragma unroll 8
    for (int k = k0; k < k0 + 512; k++) acc += phi[k] * Wt[k * 32 + o];
    red[part][o] = acc;
    __syncthreads();
    if (tid < 32)
        out[(size_t)g * 32 + tid] = red[0][tid] + red[1][tid] + red[2][tid] + red[3][tid];
}

// ---------------- launch ----------------
extern "C" void kernel_launch(void* const* d_in, const int* in_sizes, int n_in,
                              void* d_out, int out_size) {
    const float* features = (const float*)d_in[0];   // [N,64]
    const int*   edges    = (const int*)d_in[1];     // [2,E]
    const int*   batch    = (const int*)d_in[2];     // [N]
    const float* W_embed  = (const float*)d_in[3];   // [2,128,64,8]
    const float* W_mp     = (const float*)d_in[4];   // [3,2,128,128,8]
    const float* W_read   = (const float*)d_in[5];   // [2,32,128,8]
    float* out = (float*)d_out;                      // [64,32]

    float *h0, *h1, *hf, *dinv, *wtr, *sums, *cnts;
    int *deg, *off, *cur, *srcv, *bsum, *boff;
    __nv_bfloat16 *bhe, *ble, *bhm, *blm;
    cudaGetSymbolAddress((void**)&h0,   g_h0);
    cudaGetSymbolAddress((void**)&h1,   g_h1);
    cudaGetSymbolAddress((void**)&hf,   g_hf);
    cudaGetSymbolAddress((void**)&dinv, g_dinv);
    cudaGetSymbolAddress((void**)&deg,  g_deg);
    cudaGetSymbolAddress((void**)&off,  g_off);
    cudaGetSymbolAddress((void**)&cur,  g_cur);
    cudaGetSymbolAddress((void**)&srcv, g_srcv);
    cudaGetSymbolAddress((void**)&bsum, g_bsum);
    cudaGetSymbolAddress((void**)&boff, g_boff);
    cudaGetSymbolAddress((void**)&bhe,  g_bhe);
    cudaGetSymbolAddress((void**)&ble,  g_ble);
    cudaGetSymbolAddress((void**)&bhm,  g_bhm);
    cudaGetSymbolAddress((void**)&blm,  g_blm);
    cudaGetSymbolAddress((void**)&wtr,  g_wtr);
    cudaGetSymbolAddress((void**)&sums, g_sums);
    cudaGetSymbolAddress((void**)&cnts, g_cnts);

    const int* erow = edges;
    const int* ecol = edges + EE;

    cudaFuncSetAttribute(kan_hmma, cudaFuncAttributeMaxDynamicSharedMemorySize, 98304);

    const int gblocks = (NN + 127) / 128;   // 391
    const int agg_blocks = (NN * 32 + 255) / 256;
    const size_t SMB = 98304;

    // ---- weight prep (5 launches; embed variant fuses deg/sums/cnts zeroing) ----
    make_b_embed<<<(128 * 1024 + 255) / 256, 256>>>(W_embed, bhe, ble, deg, sums, cnts);
    for (int l = 0; l < 3; l++)
        make_b<<<(128 * 2048 + 255) / 256, 256>>>(
            W_mp + (size_t)l * 2 * 128 * 128 * 8,
            bhm + (size_t)l * 128 * 2048, blm + (size_t)l * 128 * 2048, 128);
    transpose_wr<<<(2048 * 32 + 255) / 256, 256>>>(W_read, wtr);

    // embed: h0 = kan(features)   [launch #6 — ncu target]
    kan_hmma<<<gblocks, 256, SMB>>>(features, 64, bhe, ble, nullptr, nullptr, h0);

    // ---- CSR build (destination-indexed, self loops appended) ----
    count_deg<<<(EE + 255) / 256, 256>>>(ecol, deg);
    const int nb = (NN + 255) / 256;  // 196
    deg_bsum<<<nb, 256>>>(deg, bsum, dinv);
    scan_bsum<<<1, 256>>>(bsum, boff, nb, off);
    scan_write<<<nb, 256>>>(deg, boff, off, cur);
    fill_csr<<<(EE + NN + 255) / 256, 256>>>(erow, ecol, cur, srcv);

    // mp 0
    kan_hmma<<<gblocks, 256, SMB>>>(h0, 128, bhm, blm, nullptr, dinv, hf);
    aggregate<<<agg_blocks, 256>>>(hf, off, srcv, h1);
    // mp 1
    kan_hmma<<<gblocks, 256, SMB>>>(h1, 128, bhm + 128 * 2048, blm + 128 * 2048, dinv, dinv, hf);
    aggregate<<<agg_blocks, 256>>>(hf, off, srcv, h0);
    // mp 2
    kan_hmma<<<gblocks, 256, SMB>>>(h0, 128, bhm + 2 * 128 * 2048, blm + 2 * 128 * 2048, dinv, dinv, hf);
    aggregate<<<agg_blocks, 256>>>(hf, off, srcv, h1);

    // pool + readout
    pool_kernel<<<250, 256>>>(h1, batch, dinv, sums, cnts);
    readout_kernel<<<GG, 128>>>(sums, cnts, wtr, out);
}